// round 16
// baseline (speedup 1.0000x reference)
#include <cuda_runtime.h>
#include <cuda_fp16.h>

// ---------------------------------------------------------------------------
// Collapsed TemporalGNN (H0 == 0 in the scan; R gate dead):
//   y    = A_hat x           (pull-gather via per-dst buckets, no atomics)
//   Hn   = (1 + tanh(-(y@Mz + cz)/2)) * tanh(y@Mh + ch) * 0.5
//   acc  = sum_t p_t * Hn ;  out = relu(acc) @ head_w + head_b
// deg = cnt + 1 (self loops). Pipeline:
//   stream0: k_fillw (edge fill || fused weights) -> k_gather -> k_node
//   streamB: k_trans (x -> f16 xT[n][b][24]) --------^
// k_node v3: t-PAIR packing. y-row half2 loads ARE (t,t+1) pairs (t is the
// contiguous axis), so a2/b2 come straight from the 3 uint4 loads (12 regs,
// zero marshalling). 4 threads per (b,node), 8 scalar h each; consts are
// broadcast-half2 from smem. Butterfly over 4 lanes for the head GEMV.
// g_cnt zero-init, re-zeroed by k_node each replay.
// ---------------------------------------------------------------------------

#define NB 4
#define NT 12
#define NN 30000
#define NH 32
#define NO 12
#define NE 240000
#define NODE_W 24               /* F_IN(2) * T(12) floats per (b,node) */
#define NQ (NODE_W / 4)
#define CAP 64
#define FILL_BLOCKS ((NE + 255) / 256)
#define TRQ (NB * NN * NQ)      /* 720000 quad-groups to transpose */
#define TR_THREADS (TRQ / 2)    /* 2 quads per thread */
#define TR_BLOCKS ((TR_THREADS + 255) / 256)
#define NODE_THREADS (NB * NN * 4)   /* 4 threads per (b,node) */

typedef unsigned long long u64;

__device__ int      g_cnt[NN];                    // zero-init; re-zeroed by k_node
__device__ unsigned g_bkt[(size_t)NN * CAP];      // src ids
__device__ __half   g_xTh[(size_t)NN * NB * NODE_W];  // f16 node-major x
__device__ __half   g_yh[(size_t)NB * NN * NODE_W];   // f16 aggregated y
__device__ float g_Mz[2 * NH];                    // NEGATED, x0.5
__device__ float g_Mh[2 * NH];
__device__ float g_cz[NH];                        // NEGATED, x0.5
__device__ float g_ch[NH];
__device__ float g_p[NT];                         // softmax * 0.5

// ---- packed-math helpers ----
__device__ __forceinline__ u64 pk(float lo, float hi) {
    u64 r; asm("mov.b64 %0, {%1, %2};" : "=l"(r) : "f"(lo), "f"(hi)); return r;
}
__device__ __forceinline__ void upk(u64 v, float& lo, float& hi) {
    asm("mov.b64 {%0, %1}, %2;" : "=f"(lo), "=f"(hi) : "l"(v));
}
__device__ __forceinline__ u64 fma2(u64 a, u64 b, u64 c) {
    u64 r; asm("fma.rn.f32x2 %0, %1, %2, %3;" : "=l"(r) : "l"(a), "l"(b), "l"(c));
    return r;
}
__device__ __forceinline__ u64 add2(u64 a, u64 b) {
    u64 r; asm("add.rn.f32x2 %0, %1, %2;" : "=l"(r) : "l"(a), "l"(b)); return r;
}
__device__ __forceinline__ unsigned tanh2(unsigned x) {
    unsigned r; asm("tanh.approx.f16x2 %0, %1;" : "=r"(r) : "r"(x)); return r;
}
__device__ __forceinline__ unsigned hfma2u(unsigned a, unsigned b, unsigned c) {
    unsigned r; asm("fma.rn.f16x2 %0, %1, %2, %3;" : "=r"(r) : "r"(a), "r"(b), "r"(c));
    return r;
}
// 4 halfs (uint2) -> float4
__device__ __forceinline__ float4 h4tof4(uint2 u) {
    float2 f0 = __half22float2(*(__half2*)&u.x);
    float2 f1 = __half22float2(*(__half2*)&u.y);
    return make_float4(f0.x, f0.y, f1.x, f1.y);
}
__device__ __forceinline__ unsigned h2u(__half2 h) { return *(unsigned*)&h; }

// Blocks [0, FILL_BLOCKS): edge fill. Block FILL_BLOCKS: weights + softmax.
__global__ void k_fillw(const int* __restrict__ ei,
                        const float* __restrict__ att,
                        const float* __restrict__ czw, const float* __restrict__ czb,
                        const float* __restrict__ lzw, const float* __restrict__ lzb,
                        const float* __restrict__ chw, const float* __restrict__ chb,
                        const float* __restrict__ lhw, const float* __restrict__ lhb) {
    if (blockIdx.x < FILL_BLOCKS) {
        int e = blockIdx.x * 256 + threadIdx.x;
        if (e >= NE) return;
        int s = __ldg(ei + e);
        int d = __ldg(ei + NE + e);
        int pos = atomicAdd(&g_cnt[d], 1);
        g_bkt[(size_t)d * CAP + pos] = (unsigned)s;
        return;
    }
    int lane = threadIdx.x & 31;
    int warp = threadIdx.x >> 5;
    if (threadIdx.x == 0) {
        float m = -1e30f;
        for (int i = 0; i < NT; i++) m = fmaxf(m, att[i]);
        float e[NT], s = 0.f;
        for (int i = 0; i < NT; i++) { e[i] = __expf(att[i] - m); s += e[i]; }
        float inv = 0.5f / s;                    // fold the 0.5 of (1-tz)/2 here
        for (int i = 0; i < NT; i++) g_p[i] = e[i] * inv;
    }
#pragma unroll
    for (int i = warp; i < 2 * NH; i += 8) {
        int gate = i >> 5;                       // 0 = z gate, 1 = h gate
        int h = i & 31;
        const float* cw = gate ? chw : czw;
        const float* cb = gate ? chb : czb;
        const float* lw = gate ? lhw : lzw;
        const float* lb = gate ? lhb : lzb;
        float w = lw[lane * NH + h];             // only first NH rows matter (H0=0)
        float m0 = cw[lane] * w;
        float m1 = cw[NH + lane] * w;
        float c  = cb[lane] * w;
#pragma unroll
        for (int off = 16; off; off >>= 1) {
            m0 += __shfl_xor_sync(0xffffffffu, m0, off);
            m1 += __shfl_xor_sync(0xffffffffu, m1, off);
            c  += __shfl_xor_sync(0xffffffffu, c, off);
        }
        if (lane == 0) {
            c += lb[h];
            if (gate == 0) {                     // negate: tanh(-az/2) = -tz
                g_Mz[h] = -0.5f * m0; g_Mz[NH + h] = -0.5f * m1; g_cz[h] = -0.5f * c;
            } else {
                g_Mh[h] = m0; g_Mh[NH + h] = m1; g_ch[h] = c;
            }
        }
    }
}

// Transpose + f16 convert: xT[n][b][24]. 2 quad-groups per thread.
__global__ void k_trans(const float* __restrict__ x) {
    int tid = blockIdx.x * 256 + threadIdx.x;
    if (tid >= TR_THREADS) return;
#pragma unroll
    for (int half = 0; half < 2; half++) {
        int i = tid + half * TR_THREADS;          // quad id in xT order
        int q = i % NQ;
        int b = (i / NQ) & 3;
        int n = i / (NQ * NB);
        float4 v = __ldg((const float4*)x + ((size_t)b * NN + n) * NQ + q);
        __half2 h0 = __floats2half2_rn(v.x, v.y);
        __half2 h1 = __floats2half2_rn(v.z, v.w);
        uint2 o;
        o.x = *(unsigned*)&h0; o.y = *(unsigned*)&h1;
        ((uint2*)g_xTh)[i] = o;
    }
}

// Gather: one warp per node, all 4 batches. One packed (src | norm_f16) word
// per edge -> ONE shuffle per edge. Norms pre-zeroed beyond cnt -> the 8-edge
// groups are conditional-free. f32 accumulation, f16 y store.
__global__ void __launch_bounds__(256)
k_gather() {
    int n    = blockIdx.x * 8 + (threadIdx.x >> 5);   // NN % 8 == 0
    int lane = threadIdx.x & 31;

    int   cnt  = g_cnt[n];
    float dinv = rsqrtf((float)(cnt + 1));            // deg = cnt + 1
    const unsigned* brow = g_bkt + (size_t)n * CAP;

    unsigned s0 = (lane < cnt) ? brow[lane] : 0u;     // coalesced 128B
    float   nm0 = (lane < cnt) ? dinv * rsqrtf((float)(g_cnt[s0] + 1)) : 0.f;
    // pack: src in low 16 (NN < 32768), f16 norm in high 16
    unsigned w0 = s0 | ((unsigned)__half_as_ushort(__float2half_rn(nm0)) << 16);

    bool act = lane < 24;
    const uint2* xTq = (const uint2*)g_xTh;

    float4 acc = make_float4(0.f, 0.f, 0.f, 0.f);
    if (act) {
        float4 xs = h4tof4(__ldg(xTq + (size_t)n * 24 + lane));
        float inv = dinv * dinv;                      // self-loop weight 1/deg
        acc.x = xs.x * inv; acc.y = xs.y * inv;
        acc.z = xs.z * inv; acc.w = xs.w * inv;
    }

    if (cnt <= 32) {
        int rc = (cnt + 7) >> 3;                      // 8-edge groups
        for (int g = 0; g < rc; g++) {
            int e = 8 * g;                            // e+i <= 31 for cnt<=32
            unsigned w_[8];
#pragma unroll
            for (int i = 0; i < 8; i++)
                w_[i] = __shfl_sync(0xffffffffu, w0, e + i);
            if (act) {
                uint2 v[8];
#pragma unroll
                for (int i = 0; i < 8; i++)
                    v[i] = __ldg(xTq + (size_t)(w_[i] & 0xFFFFu) * 24 + lane);
#pragma unroll
                for (int i = 0; i < 8; i++) {
                    float nm = __half2float(__ushort_as_half((unsigned short)(w_[i] >> 16)));
                    float4 f = h4tof4(v[i]);
                    acc.x = fmaf(nm, f.x, acc.x);
                    acc.y = fmaf(nm, f.y, acc.y);
                    acc.z = fmaf(nm, f.z, acc.z);
                    acc.w = fmaf(nm, f.w, acc.w);
                }
            }
        }
    } else {
        // Generic fallback (in-degree > 32): lane-uniform per-edge loop.
        for (int e = 0; e < cnt; e++) {
            unsigned c = brow[e];
            float nm = dinv * rsqrtf((float)(g_cnt[c] + 1));
            if (act) {
                float4 f = h4tof4(__ldg(xTq + (size_t)c * 24 + lane));
                acc.x = fmaf(nm, f.x, acc.x); acc.y = fmaf(nm, f.y, acc.y);
                acc.z = fmaf(nm, f.z, acc.z); acc.w = fmaf(nm, f.w, acc.w);
            }
        }
    }
    if (act) {
        int q = lane % 6, b = lane / 6;
        __half2 h0 = __floats2half2_rn(acc.x, acc.y);
        __half2 h1 = __floats2half2_rn(acc.z, acc.w);
        uint2 o; o.x = *(unsigned*)&h0; o.y = *(unsigned*)&h1;
        ((uint2*)g_yh)[((size_t)b * NN + n) * NQ + q] = o;
    }
}

// Pointwise collapse + head GEMV, t-PAIR packed. FOUR threads per (b,node):
// thread r handles scalar h in [8r, 8r+8). a2/b2 t-pairs come directly from
// the y-row loads. Per (h, t-pair): 6 HFMA2 + 2 tanh2 against broadcast
// consts. Head partials butterfly-summed over the 4 lanes; r==0 writes.
// First blocks also re-zero g_cnt for the next graph replay.
__global__ void __launch_bounds__(256)
k_node(const float* __restrict__ hw, const float* __restrict__ hb,
       float* __restrict__ out) {
    __shared__ unsigned s_Mz0[NH], s_Mz1[NH], s_czp[NH];   // broadcast half2
    __shared__ unsigned s_Mh0[NH], s_Mh1[NH], s_chp[NH];
    __shared__ u64 s_hwp[NH * NO / 2];
    __shared__ u64 s_hbp[NO / 2];
    __shared__ unsigned s_ph2[NT / 2];            // half2 (p_2i, p_2i+1)
    int tid = threadIdx.x;
    int gid4 = blockIdx.x * 256 + tid;

    if (gid4 < NN) g_cnt[gid4] = 0;               // reset for next replay

    if (tid < NH) {
        s_Mz0[tid] = h2u(__half2half2(__float2half_rn(g_Mz[tid])));
        s_Mz1[tid] = h2u(__half2half2(__float2half_rn(g_Mz[NH + tid])));
        s_czp[tid] = h2u(__half2half2(__float2half_rn(g_cz[tid])));
        s_Mh0[tid] = h2u(__half2half2(__float2half_rn(g_Mh[tid])));
        s_Mh1[tid] = h2u(__half2half2(__float2half_rn(g_Mh[NH + tid])));
        s_chp[tid] = h2u(__half2half2(__float2half_rn(g_ch[tid])));
    }
    if (tid < NT / 2)
        s_ph2[tid] = h2u(__floats2half2_rn(g_p[2 * tid], g_p[2 * tid + 1]));
    for (int i = tid; i < NH * NO / 2; i += 256) s_hwp[i] = ((const u64*)hw)[i];
    if (tid < NO / 2) s_hbp[tid] = ((const u64*)hb)[tid];
    __syncthreads();

    if (gid4 >= NODE_THREADS) return;

    int gid = gid4 >> 2;                          // (b,node) id = b*NN + n
    int r   = gid4 & 3;                           // h-quarter

    // y row: 24 halfs = 3 x uint4 = 12 half2, directly (t,t+1) pairs:
    // words 0..5 = feature a t-pairs, words 6..11 = feature b t-pairs.
    unsigned a2[NT / 2], b2[NT / 2];
    {
        const uint4* yq = (const uint4*)g_yh + (size_t)gid * 3;
        uint4 u0 = __ldg(yq + 0);
        uint4 u1 = __ldg(yq + 1);
        uint4 u2 = __ldg(yq + 2);
        a2[0] = u0.x; a2[1] = u0.y; a2[2] = u0.z; a2[3] = u0.w;
        a2[4] = u1.x; a2[5] = u1.y;
        b2[0] = u1.z; b2[1] = u1.w;
        b2[2] = u2.x; b2[3] = u2.y; b2[4] = u2.z; b2[5] = u2.w;
    }
    unsigned ph_[NT / 2];
#pragma unroll
    for (int i = 0; i < NT / 2; i++) ph_[i] = s_ph2[i];

    u64 o2[NO / 2];
#pragma unroll
    for (int j = 0; j < NO / 2; j++) o2[j] = 0ULL;

    int hbase = r * 8;
#pragma unroll 1
    for (int hh = 0; hh < 8; hh++) {              // this thread's scalar h
        int h = hbase + hh;
        unsigned mz0 = s_Mz0[h], mz1 = s_Mz1[h], czc = s_czp[h];
        unsigned mh0 = s_Mh0[h], mh1 = s_Mh1[h], chc = s_chp[h];
        unsigned acc = 0;                         // half2: partial sums (t even, t odd)
#pragma unroll
        for (int tp = 0; tp < NT / 2; tp++) {
            unsigned azn = hfma2u(a2[tp], mz0, hfma2u(b2[tp], mz1, czc)); // -(az)/2
            unsigned ahp = hfma2u(a2[tp], mh0, hfma2u(b2[tp], mh1, chc));
            unsigned tzn = tanh2(azn);            // = -tz (odd fn, consts negated)
            unsigned th  = tanh2(ahp);
            unsigned u   = hfma2u(tzn, th, th);   // (1 - tz) * th
            acc = hfma2u(ph_[tp], u, acc);
        }
        __half2 ah2 = *(__half2*)&acc;
        float hn = fmaxf(__low2float(ah2) + __high2float(ah2), 0.f);  // relu
        u64 hn2 = pk(hn, hn);
        const u64* w = &s_hwp[h * (NO / 2)];
#pragma unroll
        for (int j = 0; j < NO / 2; j++)
            o2[j] = fma2(hn2, w[j], o2[j]);
    }

    // Combine the four h-quarters (lanes r, r^1, r^2) and write from r == 0.
#pragma unroll
    for (int off = 1; off < 4; off <<= 1) {
#pragma unroll
        for (int j = 0; j < NO / 2; j++)
            o2[j] = add2(o2[j], __shfl_xor_sync(0xffffffffu, o2[j], off));
    }

    if (r == 0) {
        float of[NO];
#pragma unroll
        for (int j = 0; j < NO / 2; j++) {
            u64 v = add2(o2[j], s_hbp[j]);
            upk(v, of[2 * j], of[2 * j + 1]);
        }
        float4* op4 = (float4*)(out + (size_t)gid * NO);
#pragma unroll
        for (int j = 0; j < NO / 4; j++)
            op4[j] = make_float4(of[4 * j], of[4 * j + 1], of[4 * j + 2], of[4 * j + 3]);
    }
}

extern "C" void kernel_launch(void* const* d_in, const int* in_sizes, int n_in,
                              void* d_out, int out_size) {
    const float* x   = (const float*)d_in[0];
    const int*   ei  = (const int*)d_in[1];
    const float* att = (const float*)d_in[2];
    const float* czw = (const float*)d_in[3];
    const float* czb = (const float*)d_in[4];
    const float* lzw = (const float*)d_in[5];
    const float* lzb = (const float*)d_in[6];
    // d_in[7..10] = conv_r_*, lin_r_* : dead (H0 == 0 -> H0*R == 0)
    const float* chw = (const float*)d_in[11];
    const float* chb = (const float*)d_in[12];
    const float* lhw = (const float*)d_in[13];
    const float* lhb = (const float*)d_in[14];
    const float* hw  = (const float*)d_in[15];
    const float* hb  = (const float*)d_in[16];
    float* out = (float*)d_out;

    // Host-side resources created once on the first (uncaptured correctness)
    // call. Device work per call is identical -> deterministic & capturable.
    static cudaStream_t sB = nullptr;
    static cudaEvent_t eF = nullptr, eB = nullptr;
    if (sB == nullptr) {
        cudaStreamCreateWithFlags(&sB, cudaStreamNonBlocking);
        cudaEventCreateWithFlags(&eF, cudaEventDisableTiming);
        cudaEventCreateWithFlags(&eB, cudaEventDisableTiming);
    }

    // Fork: bring the transpose stream into the capture graph.
    cudaEventRecord(eF, 0);
    cudaStreamWaitEvent(sB, eF, 0);

    k_fillw<<<FILL_BLOCKS + 1, 256>>>(ei, att, czw, czb, lzw, lzb,
                                      chw, chb, lhw, lhb);  // stream 0
    k_trans<<<TR_BLOCKS, 256, 0, sB>>>(x);                  // stream B

    // Join B before gather (needs buckets + f16 xT).
    cudaEventRecord(eB, sB);
    cudaStreamWaitEvent(0, eB, 0);
    k_gather<<<NN / 8, 256>>>();

    k_node<<<(NODE_THREADS + 255) / 256, 256>>>(hw, hb, out);
}

// round 17
// speedup vs baseline: 1.0942x; 1.0942x over previous
#include <cuda_runtime.h>
#include <cuda_fp16.h>

// ---------------------------------------------------------------------------
// Collapsed TemporalGNN (H0 == 0 in the scan; R gate dead):
//   y    = A_hat x           (pull-gather via per-dst buckets, no atomics)
//   Hn   = (1 + tanh(-(y@Mz + cz)/2)) * tanh(y@Mh + ch) * 0.5
//   acc  = sum_t p_t * Hn ;  out = relu(acc) @ head_w + head_b
// deg = cnt + 1 (self loops). CHUNKED pipeline (gather || node overlap):
//   s0: k_fillw ─► k_gather[0,N/2) ─► k_gather[N/2,N) ─► k_node1 (+cnt reset)
//   sB: k_trans ─┘        └─(event)─► k_node0 (overlaps gather1)
// k_node = R15 form: 2 threads per (b,node), h-pair f16x2 gate math.
// g_cnt zero-init; re-zeroed ONLY by node chunk 1 (after all gathers).
// ---------------------------------------------------------------------------

#define NB 4
#define NT 12
#define NN 30000
#define NCH (NN / 2)            /* nodes per chunk */
#define NH 32
#define NO 12
#define NE 240000
#define NODE_W 24               /* F_IN(2) * T(12) floats per (b,node) */
#define NQ (NODE_W / 4)
#define CAP 64
#define FILL_BLOCKS ((NE + 255) / 256)
#define TRQ (NB * NN * NQ)      /* 720000 quad-groups to transpose */
#define TR_THREADS (TRQ / 2)    /* 2 quads per thread */
#define TR_BLOCKS ((TR_THREADS + 255) / 256)
#define CH_THREADS (NB * NCH * 2)    /* node threads per chunk */

typedef unsigned long long u64;

__device__ int      g_cnt[NN];                    // zero-init; reset by node1
__device__ unsigned g_bkt[(size_t)NN * CAP];      // src ids
__device__ __half   g_xTh[(size_t)NN * NB * NODE_W];  // f16 node-major x
__device__ __half   g_yh[(size_t)NB * NN * NODE_W];   // f16 aggregated y
__device__ float g_Mz[2 * NH];                    // NEGATED, x0.5
__device__ float g_Mh[2 * NH];
__device__ float g_cz[NH];                        // NEGATED, x0.5
__device__ float g_ch[NH];
__device__ float g_p[NT];                         // softmax * 0.5

// ---- packed-math helpers ----
__device__ __forceinline__ u64 pk(float lo, float hi) {
    u64 r; asm("mov.b64 %0, {%1, %2};" : "=l"(r) : "f"(lo), "f"(hi)); return r;
}
__device__ __forceinline__ void upk(u64 v, float& lo, float& hi) {
    asm("mov.b64 {%0, %1}, %2;" : "=f"(lo), "=f"(hi) : "l"(v));
}
__device__ __forceinline__ u64 fma2(u64 a, u64 b, u64 c) {
    u64 r; asm("fma.rn.f32x2 %0, %1, %2, %3;" : "=l"(r) : "l"(a), "l"(b), "l"(c));
    return r;
}
__device__ __forceinline__ u64 add2(u64 a, u64 b) {
    u64 r; asm("add.rn.f32x2 %0, %1, %2;" : "=l"(r) : "l"(a), "l"(b)); return r;
}
__device__ __forceinline__ unsigned tanh2(unsigned x) {
    unsigned r; asm("tanh.approx.f16x2 %0, %1;" : "=r"(r) : "r"(x)); return r;
}
__device__ __forceinline__ unsigned hfma2u(unsigned a, unsigned b, unsigned c) {
    unsigned r; asm("fma.rn.f16x2 %0, %1, %2, %3;" : "=r"(r) : "r"(a), "r"(b), "r"(c));
    return r;
}
// 4 halfs (uint2) -> float4
__device__ __forceinline__ float4 h4tof4(uint2 u) {
    float2 f0 = __half22float2(*(__half2*)&u.x);
    float2 f1 = __half22float2(*(__half2*)&u.y);
    return make_float4(f0.x, f0.y, f1.x, f1.y);
}
__device__ __forceinline__ unsigned h2u(__half2 h) { return *(unsigned*)&h; }

// Blocks [0, FILL_BLOCKS): edge fill. Block FILL_BLOCKS: weights + softmax.
__global__ void k_fillw(const int* __restrict__ ei,
                        const float* __restrict__ att,
                        const float* __restrict__ czw, const float* __restrict__ czb,
                        const float* __restrict__ lzw, const float* __restrict__ lzb,
                        const float* __restrict__ chw, const float* __restrict__ chb,
                        const float* __restrict__ lhw, const float* __restrict__ lhb) {
    if (blockIdx.x < FILL_BLOCKS) {
        int e = blockIdx.x * 256 + threadIdx.x;
        if (e >= NE) return;
        int s = __ldg(ei + e);
        int d = __ldg(ei + NE + e);
        int pos = atomicAdd(&g_cnt[d], 1);
        g_bkt[(size_t)d * CAP + pos] = (unsigned)s;
        return;
    }
    int lane = threadIdx.x & 31;
    int warp = threadIdx.x >> 5;
    if (threadIdx.x == 0) {
        float m = -1e30f;
        for (int i = 0; i < NT; i++) m = fmaxf(m, att[i]);
        float e[NT], s = 0.f;
        for (int i = 0; i < NT; i++) { e[i] = __expf(att[i] - m); s += e[i]; }
        float inv = 0.5f / s;                    // fold the 0.5 of (1-tz)/2 here
        for (int i = 0; i < NT; i++) g_p[i] = e[i] * inv;
    }
#pragma unroll
    for (int i = warp; i < 2 * NH; i += 8) {
        int gate = i >> 5;                       // 0 = z gate, 1 = h gate
        int h = i & 31;
        const float* cw = gate ? chw : czw;
        const float* cb = gate ? chb : czb;
        const float* lw = gate ? lhw : lzw;
        const float* lb = gate ? lhb : lzb;
        float w = lw[lane * NH + h];             // only first NH rows matter (H0=0)
        float m0 = cw[lane] * w;
        float m1 = cw[NH + lane] * w;
        float c  = cb[lane] * w;
#pragma unroll
        for (int off = 16; off; off >>= 1) {
            m0 += __shfl_xor_sync(0xffffffffu, m0, off);
            m1 += __shfl_xor_sync(0xffffffffu, m1, off);
            c  += __shfl_xor_sync(0xffffffffu, c, off);
        }
        if (lane == 0) {
            c += lb[h];
            if (gate == 0) {                     // negate: tanh(-az/2) = -tz
                g_Mz[h] = -0.5f * m0; g_Mz[NH + h] = -0.5f * m1; g_cz[h] = -0.5f * c;
            } else {
                g_Mh[h] = m0; g_Mh[NH + h] = m1; g_ch[h] = c;
            }
        }
    }
}

// Transpose + f16 convert: xT[n][b][24]. 2 quad-groups per thread.
__global__ void k_trans(const float* __restrict__ x) {
    int tid = blockIdx.x * 256 + threadIdx.x;
    if (tid >= TR_THREADS) return;
#pragma unroll
    for (int half = 0; half < 2; half++) {
        int i = tid + half * TR_THREADS;          // quad id in xT order
        int q = i % NQ;
        int b = (i / NQ) & 3;
        int n = i / (NQ * NB);
        float4 v = __ldg((const float4*)x + ((size_t)b * NN + n) * NQ + q);
        __half2 h0 = __floats2half2_rn(v.x, v.y);
        __half2 h1 = __floats2half2_rn(v.z, v.w);
        uint2 o;
        o.x = *(unsigned*)&h0; o.y = *(unsigned*)&h1;
        ((uint2*)g_xTh)[i] = o;
    }
}

// Gather for node range [n_base, n_base + NCH). One warp per node.
// One packed (src | norm_f16) word per edge -> ONE shuffle per edge.
__global__ void __launch_bounds__(256)
k_gather(int n_base) {
    int n    = n_base + blockIdx.x * 8 + (threadIdx.x >> 5);  // NCH % 8 == 0
    int lane = threadIdx.x & 31;

    int   cnt  = g_cnt[n];
    float dinv = rsqrtf((float)(cnt + 1));            // deg = cnt + 1
    const unsigned* brow = g_bkt + (size_t)n * CAP;

    unsigned s0 = (lane < cnt) ? brow[lane] : 0u;     // coalesced 128B
    float   nm0 = (lane < cnt) ? dinv * rsqrtf((float)(g_cnt[s0] + 1)) : 0.f;
    // pack: src in low 16 (NN < 32768), f16 norm in high 16
    unsigned w0 = s0 | ((unsigned)__half_as_ushort(__float2half_rn(nm0)) << 16);

    bool act = lane < 24;
    const uint2* xTq = (const uint2*)g_xTh;

    float4 acc = make_float4(0.f, 0.f, 0.f, 0.f);
    if (act) {
        float4 xs = h4tof4(__ldg(xTq + (size_t)n * 24 + lane));
        float inv = dinv * dinv;                      // self-loop weight 1/deg
        acc.x = xs.x * inv; acc.y = xs.y * inv;
        acc.z = xs.z * inv; acc.w = xs.w * inv;
    }

    if (cnt <= 32) {
        int rc = (cnt + 7) >> 3;                      // 8-edge groups
        for (int g = 0; g < rc; g++) {
            int e = 8 * g;                            // e+i <= 31 for cnt<=32
            unsigned w_[8];
#pragma unroll
            for (int i = 0; i < 8; i++)
                w_[i] = __shfl_sync(0xffffffffu, w0, e + i);
            if (act) {
                uint2 v[8];
#pragma unroll
                for (int i = 0; i < 8; i++)
                    v[i] = __ldg(xTq + (size_t)(w_[i] & 0xFFFFu) * 24 + lane);
#pragma unroll
                for (int i = 0; i < 8; i++) {
                    float nm = __half2float(__ushort_as_half((unsigned short)(w_[i] >> 16)));
                    float4 f = h4tof4(v[i]);
                    acc.x = fmaf(nm, f.x, acc.x);
                    acc.y = fmaf(nm, f.y, acc.y);
                    acc.z = fmaf(nm, f.z, acc.z);
                    acc.w = fmaf(nm, f.w, acc.w);
                }
            }
        }
    } else {
        // Generic fallback (in-degree > 32): lane-uniform per-edge loop.
        for (int e = 0; e < cnt; e++) {
            unsigned c = brow[e];
            float nm = dinv * rsqrtf((float)(g_cnt[c] + 1));
            if (act) {
                float4 f = h4tof4(__ldg(xTq + (size_t)c * 24 + lane));
                acc.x = fmaf(nm, f.x, acc.x); acc.y = fmaf(nm, f.y, acc.y);
                acc.z = fmaf(nm, f.z, acc.z); acc.w = fmaf(nm, f.w, acc.w);
            }
        }
    }
    if (act) {
        int q = lane % 6, b = lane / 6;
        __half2 h0 = __floats2half2_rn(acc.x, acc.y);
        __half2 h1 = __floats2half2_rn(acc.z, acc.w);
        uint2 o; o.x = *(unsigned*)&h0; o.y = *(unsigned*)&h1;
        ((uint2*)g_yh)[((size_t)b * NN + n) * NQ + q] = o;
    }
}

// Pointwise collapse + head GEMV for node range [n_base, n_base + NCH).
// TWO threads per (b,node): thread r handles h-pairs [8r, 8r+8). Partial
// head GEMV summed via shfl_xor(1); r==0 writes. Chunk 1 (do_reset) also
// re-zeroes g_cnt for the next graph replay (safe: all gathers are done).
__global__ void __launch_bounds__(256)
k_node(const float* __restrict__ hw, const float* __restrict__ hb,
       float* __restrict__ out, int n_base, int do_reset) {
    __shared__ unsigned s_Mz0[16], s_Mz1[16], s_czp[16];   // half2 per h-pair
    __shared__ unsigned s_Mh0[16], s_Mh1[16], s_chp[16];
    __shared__ u64 s_hwp[NH * NO / 2];
    __shared__ u64 s_hbp[NO / 2];
    __shared__ unsigned s_ph[NT];
    int tid = threadIdx.x;
    int gid2 = blockIdx.x * 256 + tid;

    if (do_reset && gid2 < NN) g_cnt[gid2] = 0;   // reset for next replay

    if (tid < 16) {
        s_Mz0[tid] = h2u(__floats2half2_rn(g_Mz[2 * tid], g_Mz[2 * tid + 1]));
        s_Mz1[tid] = h2u(__floats2half2_rn(g_Mz[NH + 2 * tid], g_Mz[NH + 2 * tid + 1]));
        s_czp[tid] = h2u(__floats2half2_rn(g_cz[2 * tid], g_cz[2 * tid + 1]));
        s_Mh0[tid] = h2u(__floats2half2_rn(g_Mh[2 * tid], g_Mh[2 * tid + 1]));
        s_Mh1[tid] = h2u(__floats2half2_rn(g_Mh[NH + 2 * tid], g_Mh[NH + 2 * tid + 1]));
        s_chp[tid] = h2u(__floats2half2_rn(g_ch[2 * tid], g_ch[2 * tid + 1]));
    }
    if (tid < NT) s_ph[tid] = h2u(__float2half2_rn(g_p[tid]));
    for (int i = tid; i < NH * NO / 2; i += 256) s_hwp[i] = ((const u64*)hw)[i];
    if (tid < NO / 2) s_hbp[tid] = ((const u64*)hb)[tid];
    __syncthreads();

    if (gid2 >= CH_THREADS) return;

    int local = gid2 >> 1;                        // chunk-local (b, n) index
    int r     = gid2 & 1;                         // which half of h
    int b     = local / NCH;
    int n     = n_base + (local % NCH);
    int gid   = b * NN + n;                       // global (b,node) id

    // y row: 24 halfs = 48B = 3 x uint4 (same row read by both threads; L1).
    __half yh[NODE_W];
    const uint4* yq = (const uint4*)g_yh + (size_t)gid * 3;
#pragma unroll
    for (int i = 0; i < 3; i++) {
        uint4 u = __ldg(yq + i);
        *(uint4*)(yh + 8 * i) = u;
    }
    unsigned a2[NT], b2[NT];
#pragma unroll
    for (int t = 0; t < NT; t++) {
        a2[t] = h2u(__half2half2(yh[t]));
        b2[t] = h2u(__half2half2(yh[NT + t]));
    }
    unsigned ph_[NT];
#pragma unroll
    for (int t = 0; t < NT; t++) ph_[t] = s_ph[t];

    u64 o2[NO / 2];
#pragma unroll
    for (int j = 0; j < NO / 2; j++) o2[j] = 0ULL;

    int kbase = r * 8;
#pragma unroll 1
    for (int kk = 0; kk < 8; kk++) {              // this thread's h-pairs
        int k = kbase + kk;
        unsigned mz0 = s_Mz0[k], mz1 = s_Mz1[k], czc = s_czp[k];
        unsigned mh0 = s_Mh0[k], mh1 = s_Mh1[k], chc = s_chp[k];
        unsigned acc = 0;                         // half2 zero
#pragma unroll
        for (int t = 0; t < NT; t++) {
            unsigned azn = hfma2u(a2[t], mz0, hfma2u(b2[t], mz1, czc)); // -(az)/2
            unsigned ahp = hfma2u(a2[t], mh0, hfma2u(b2[t], mh1, chc));
            unsigned tzn = tanh2(azn);            // = -tz (odd fn, consts negated)
            unsigned th  = tanh2(ahp);
            unsigned u   = hfma2u(tzn, th, th);   // (1 - tz) * th
            acc = hfma2u(ph_[t], u, acc);
        }
        __half2 ah2 = *(__half2*)&acc;
        float rl = fmaxf(__low2float(ah2), 0.f);  // relu, h = 2k
        float rh = fmaxf(__high2float(ah2), 0.f); // h = 2k+1
        u64 rl2 = pk(rl, rl), rh2 = pk(rh, rh);
        const u64* w0 = &s_hwp[(2 * k) * (NO / 2)];
        const u64* w1 = &s_hwp[(2 * k + 1) * (NO / 2)];
#pragma unroll
        for (int j = 0; j < NO / 2; j++)
            o2[j] = fma2(rl2, w0[j], fma2(rh2, w1[j], o2[j]));
    }

    // Combine the two halves (adjacent lanes) and write from r == 0.
#pragma unroll
    for (int j = 0; j < NO / 2; j++)
        o2[j] = add2(o2[j], __shfl_xor_sync(0xffffffffu, o2[j], 1));

    if (r == 0) {
        float of[NO];
#pragma unroll
        for (int j = 0; j < NO / 2; j++) {
            u64 v = add2(o2[j], s_hbp[j]);
            upk(v, of[2 * j], of[2 * j + 1]);
        }
        float4* op4 = (float4*)(out + (size_t)gid * NO);
#pragma unroll
        for (int j = 0; j < NO / 4; j++)
            op4[j] = make_float4(of[4 * j], of[4 * j + 1], of[4 * j + 2], of[4 * j + 3]);
    }
}

extern "C" void kernel_launch(void* const* d_in, const int* in_sizes, int n_in,
                              void* d_out, int out_size) {
    const float* x   = (const float*)d_in[0];
    const int*   ei  = (const int*)d_in[1];
    const float* att = (const float*)d_in[2];
    const float* czw = (const float*)d_in[3];
    const float* czb = (const float*)d_in[4];
    const float* lzw = (const float*)d_in[5];
    const float* lzb = (const float*)d_in[6];
    // d_in[7..10] = conv_r_*, lin_r_* : dead (H0 == 0 -> H0*R == 0)
    const float* chw = (const float*)d_in[11];
    const float* chb = (const float*)d_in[12];
    const float* lhw = (const float*)d_in[13];
    const float* lhb = (const float*)d_in[14];
    const float* hw  = (const float*)d_in[15];
    const float* hb  = (const float*)d_in[16];
    float* out = (float*)d_out;

    // Host-side resources created once on the first (uncaptured correctness)
    // call. Device work per call is identical -> deterministic & capturable.
    static cudaStream_t sB = nullptr;
    static cudaEvent_t eF = nullptr, eB = nullptr, eG0 = nullptr, eN0 = nullptr;
    if (sB == nullptr) {
        cudaStreamCreateWithFlags(&sB, cudaStreamNonBlocking);
        cudaEventCreateWithFlags(&eF, cudaEventDisableTiming);
        cudaEventCreateWithFlags(&eB, cudaEventDisableTiming);
        cudaEventCreateWithFlags(&eG0, cudaEventDisableTiming);
        cudaEventCreateWithFlags(&eN0, cudaEventDisableTiming);
    }

    const int CH_BLOCKS = (CH_THREADS + 255) / 256;

    // Fork: bring the transpose stream into the capture graph.
    cudaEventRecord(eF, 0);
    cudaStreamWaitEvent(sB, eF, 0);

    k_fillw<<<FILL_BLOCKS + 1, 256>>>(ei, att, czw, czb, lzw, lzb,
                                      chw, chb, lhw, lhb);  // stream 0
    k_trans<<<TR_BLOCKS, 256, 0, sB>>>(x);                  // stream B

    // Join trans before the first gather (needs buckets + f16 xT).
    cudaEventRecord(eB, sB);
    cudaStreamWaitEvent(0, eB, 0);

    k_gather<<<NCH / 8, 256>>>(0);                          // chunk 0
    cudaEventRecord(eG0, 0);

    k_gather<<<NCH / 8, 256>>>(NCH);                        // chunk 1

    // node0 overlaps gather1 on stream B.
    cudaStreamWaitEvent(sB, eG0, 0);
    k_node<<<CH_BLOCKS, 256, 0, sB>>>(hw, hb, out, 0, 0);   // no cnt reset

    // node1 after gather1 (stream order); resets g_cnt (all gathers done).
    k_node<<<CH_BLOCKS, 256>>>(hw, hb, out, NCH, 1);

    // Join node0 back so the graph's end depends on both halves.
    cudaEventRecord(eN0, sB);
    cudaStreamWaitEvent(0, eN0, 0);
}